// round 10
// baseline (speedup 1.0000x reference)
#include <cuda_runtime.h>
#include <math.h>
#include <stdint.h>

#define S_LEN 4096
#define D_MODEL 1024
#define N_HEADS 16
#define D_HEAD 64

// Scratch (allocation-free rule: __device__ globals)
__device__ float g_Qp[S_LEN * D_MODEL];
__device__ float g_Kp[S_LEN * D_MODEL];
__device__ float g_Vp[S_LEN * D_MODEL];
__device__ float g_vals[S_LEN * D_MODEL];
__device__ float g_Wt[4 * D_MODEL * D_MODEL];     // transposed tf32 weights
__device__ float g_inv[(size_t)N_HEADS * S_LEN];  // 1 / rowsum
__device__ float g_attn_fallback[(size_t)N_HEADS * S_LEN * S_LEN];

__device__ __forceinline__ float to_tf32(float x) {
    float y;
    asm("cvt.rna.tf32.f32 %0, %1;" : "=f"(y) : "f"(x));
    return y;
}

__device__ __forceinline__ float4 tf32_4(float4 f) {
    return make_float4(to_tf32(f.x), to_tf32(f.y), to_tf32(f.z), to_tf32(f.w));
}

__device__ __forceinline__ uint32_t smem_u32(const void* p) {
    return (uint32_t)__cvta_generic_to_shared(p);
}

__device__ __forceinline__ void ldsm_x4(uint32_t& r0, uint32_t& r1,
                                        uint32_t& r2, uint32_t& r3, uint32_t addr)
{
    asm volatile("ldmatrix.sync.aligned.m8n8.x4.shared.b16 {%0,%1,%2,%3}, [%4];"
                 : "=r"(r0), "=r"(r1), "=r"(r2), "=r"(r3) : "r"(addr));
}

__device__ __forceinline__ void mma_tf32u(float& d0, float& d1, float& d2, float& d3,
                                          uint32_t a0, uint32_t a1, uint32_t a2, uint32_t a3,
                                          uint32_t b0, uint32_t b1)
{
    asm volatile(
        "mma.sync.aligned.m16n8k8.row.col.f32.tf32.tf32.f32 "
        "{%0,%1,%2,%3}, {%4,%5,%6,%7}, {%8,%9}, {%0,%1,%2,%3};"
        : "+f"(d0), "+f"(d1), "+f"(d2), "+f"(d3)
        : "r"(a0), "r"(a1), "r"(a2), "r"(a3), "r"(b0), "r"(b1));
}

// ---------------------------------------------------------------------------
// Weight transpose: Wt[z][n][k] = tf32(W[z][k][n]).  grid (32,32,4), block (32,8)
// ---------------------------------------------------------------------------
__global__ void transpose_w(const float* __restrict__ W0, const float* __restrict__ W1,
                            const float* __restrict__ W2, const float* __restrict__ W3,
                            float* __restrict__ Wt)
{
    const float* W = (blockIdx.z == 0) ? W0 : (blockIdx.z == 1) ? W1
                   : (blockIdx.z == 2) ? W2 : W3;
    float* T = Wt + (size_t)blockIdx.z * D_MODEL * D_MODEL;
    __shared__ float t[32][33];
    int x = blockIdx.x * 32 + threadIdx.x;
    int y0 = blockIdx.y * 32;
    #pragma unroll
    for (int i = threadIdx.y; i < 32; i += 8)
        t[i][threadIdx.x] = W[(long)(y0 + i) * D_MODEL + x];
    __syncthreads();
    int xo = y0 + threadIdx.x;
    int yo0 = blockIdx.x * 32;
    #pragma unroll
    for (int i = threadIdx.y; i < 32; i += 8)
        T[(long)(yo0 + i) * D_MODEL + xo] = to_tf32(t[threadIdx.x][i]);
}

// ---------------------------------------------------------------------------
// NT projection: C = A @ Bt^T + bias.  A [4096,1024] fp32 (cvt at staging),
// Bt [1024,1024] already tf32.  BM=BN=128, BK=32, dual-LDSM fragments.
// CVT_OUT: round outputs to tf32 (for Qp/Kp/Vp) or keep fp32 (final out).
// ---------------------------------------------------------------------------
template <bool CVT_OUT>
__device__ __forceinline__ void proj_nt(const float* __restrict__ A,
                                        const float* __restrict__ Bt,
                                        float* __restrict__ C,
                                        const float* __restrict__ bias)
{
    __shared__ __align__(16) float As[128][36];
    __shared__ __align__(16) float Bs[128][36];

    const int m0 = blockIdx.y * 128;
    const int n0 = blockIdx.x * 128;
    const int tid = threadIdx.x;
    const int warp = tid >> 5;
    const int lane = tid & 31;
    const int gid = lane >> 2;
    const int tig = lane & 3;
    const int wm0 = (warp >> 1) * 32;
    const int wn0 = (warp & 1) * 64;

    const int arow = lane & 15;
    const int acol = (lane >> 4) << 2;
    const int brow = (lane & 7) + ((lane >> 4) << 3);
    const int bcol = ((lane >> 3) & 1) << 2;

    uint32_t aaddr[2];
    #pragma unroll
    for (int mi = 0; mi < 2; mi++)
        aaddr[mi] = smem_u32(&As[wm0 + mi * 16 + arow][acol]);
    uint32_t baddr[4];
    #pragma unroll
    for (int p = 0; p < 4; p++)
        baddr[p] = smem_u32(&Bs[wn0 + p * 16 + brow][bcol]);

    float acc[2][8][4];
    #pragma unroll
    for (int mi = 0; mi < 2; mi++)
        #pragma unroll
        for (int ni = 0; ni < 8; ni++)
            #pragma unroll
            for (int j = 0; j < 4; j++) acc[mi][ni][j] = 0.f;

    for (int k0 = 0; k0 < D_MODEL; k0 += 32) {
        #pragma unroll
        for (int i = 0; i < 4; i++) {
            int idx = tid + i * 256;
            int r = idx >> 3;
            int kq = (idx & 7) * 4;
            *(float4*)&As[r][kq] =
                tf32_4(*(const float4*)(A + (long)(m0 + r) * D_MODEL + k0 + kq));
            *(float4*)&Bs[r][kq] =
                *(const float4*)(Bt + (long)(n0 + r) * D_MODEL + k0 + kq);
        }
        __syncthreads();

        #pragma unroll
        for (int ksi = 0; ksi < 4; ksi++) {
            const uint32_t koff = ksi * 8 * 4;
            uint32_t a[2][4];
            #pragma unroll
            for (int mi = 0; mi < 2; mi++)
                ldsm_x4(a[mi][0], a[mi][1], a[mi][2], a[mi][3], aaddr[mi] + koff);
            uint32_t b[4][4];
            #pragma unroll
            for (int p = 0; p < 4; p++)
                ldsm_x4(b[p][0], b[p][1], b[p][2], b[p][3], baddr[p] + koff);
            #pragma unroll
            for (int mi = 0; mi < 2; mi++)
                #pragma unroll
                for (int ni = 0; ni < 8; ni++) {
                    int p = ni >> 1, hi = (ni & 1) << 1;
                    mma_tf32u(acc[mi][ni][0], acc[mi][ni][1], acc[mi][ni][2], acc[mi][ni][3],
                              a[mi][0], a[mi][1], a[mi][2], a[mi][3],
                              b[p][hi], b[p][hi + 1]);
                }
        }
        __syncthreads();
    }

    #pragma unroll
    for (int mi = 0; mi < 2; mi++) {
        int r0 = m0 + wm0 + mi * 16 + gid;
        #pragma unroll
        for (int ni = 0; ni < 8; ni++) {
            int c = n0 + wn0 + ni * 8 + tig * 2;
            float b0 = bias[c], b1 = bias[c + 1];
            float v0 = acc[mi][ni][0] + b0, v1 = acc[mi][ni][1] + b1;
            float v2 = acc[mi][ni][2] + b0, v3 = acc[mi][ni][3] + b1;
            if (CVT_OUT) {
                v0 = to_tf32(v0); v1 = to_tf32(v1);
                v2 = to_tf32(v2); v3 = to_tf32(v3);
            }
            *(float2*)&C[(long)r0 * D_MODEL + c] = make_float2(v0, v1);
            *(float2*)&C[(long)(r0 + 8) * D_MODEL + c] = make_float2(v2, v3);
        }
    }
}

// QKV projections in one launch (z selects which projection); outputs tf32.
__global__ void __launch_bounds__(256, 2)
qkv_proj(const float* __restrict__ q, const float* __restrict__ k,
         const float* __restrict__ v, const float* __restrict__ Wt,
         const float* __restrict__ bq, const float* __restrict__ bk,
         const float* __restrict__ bv,
         float* __restrict__ Qp, float* __restrict__ Kp, float* __restrict__ Vp)
{
    int z = blockIdx.z;
    const float* A = (z == 0) ? q : (z == 1) ? k : v;
    const float* Bt = Wt + (size_t)z * D_MODEL * D_MODEL;
    const float* bias = (z == 0) ? bq : (z == 1) ? bk : bv;
    float* C = (z == 0) ? Qp : (z == 1) ? Kp : Vp;
    proj_nt<true>(A, Bt, C, bias);
}

// Output projection; full fp32 output.
__global__ void __launch_bounds__(256, 2)
o_proj(const float* __restrict__ A, const float* __restrict__ Wt,
       float* __restrict__ C, const float* __restrict__ bias)
{
    proj_nt<false>(A, Wt + (size_t)3 * D_MODEL * D_MODEL, C, bias);
}

// ---------------------------------------------------------------------------
// Rowsum pass (inputs already tf32 -> plain copies, LDSM fragments).
// ---------------------------------------------------------------------------
__global__ void __launch_bounds__(256, 2)
rowsum_kernel(const float* __restrict__ Qp, const float* __restrict__ Kp,
              float* __restrict__ inv, float scale)
{
    extern __shared__ __align__(16) float sm[];
    float (*Qs)[D_HEAD + 4] = (float (*)[D_HEAD + 4])sm;
    float (*Ks)[D_HEAD + 4] = (float (*)[D_HEAD + 4])(sm + 128 * (D_HEAD + 4));
    __shared__ float red[2][128];

    const int mb = blockIdx.x, h = blockIdx.y;
    const float* Aq = Qp + (long)mb * 128 * D_MODEL + h * D_HEAD;

    const int tid = threadIdx.x;
    const int warp = tid >> 5;
    const int lane = tid & 31;
    const int gid = lane >> 2;
    const int tig = lane & 3;
    const int wm0 = (warp >> 1) * 32;
    const int wn = warp & 1;
    const int wn0 = wn * 64;

    const int arow = lane & 15;
    const int acol = (lane >> 4) << 2;
    const int brow = (lane & 7) + ((lane >> 4) << 3);
    const int bcol = ((lane >> 3) & 1) << 2;

    #pragma unroll
    for (int i = 0; i < 8; i++) {
        int idx = tid + i * 256;
        int r = idx >> 4;
        int c4 = (idx & 15) * 4;
        *(float4*)&Qs[r][c4] = *(const float4*)(Aq + (long)r * D_MODEL + c4);
    }

    uint32_t qa[2];
    #pragma unroll
    for (int mi = 0; mi < 2; mi++)
        qa[mi] = smem_u32(&Qs[wm0 + mi * 16 + arow][acol]);
    uint32_t kb[4];
    #pragma unroll
    for (int p = 0; p < 4; p++)
        kb[p] = smem_u32(&Ks[wn0 + p * 16 + brow][bcol]);

    float rp[2][2] = {{0.f, 0.f}, {0.f, 0.f}};

    for (int nb = 0; nb < S_LEN / 128; nb++) {
        const float* Bk = Kp + (long)nb * 128 * D_MODEL + h * D_HEAD;
        __syncthreads();
        #pragma unroll
        for (int i = 0; i < 8; i++) {
            int idx = tid + i * 256;
            int r = idx >> 4;
            int c4 = (idx & 15) * 4;
            *(float4*)&Ks[r][c4] = *(const float4*)(Bk + (long)r * D_MODEL + c4);
        }
        __syncthreads();

        float acc[2][8][4];
        #pragma unroll
        for (int mi = 0; mi < 2; mi++)
            #pragma unroll
            for (int ni = 0; ni < 8; ni++)
                #pragma unroll
                for (int j = 0; j < 4; j++) acc[mi][ni][j] = 0.f;

        #pragma unroll
        for (int ksi = 0; ksi < 8; ksi++) {
            const uint32_t koff = ksi * 8 * 4;
            uint32_t a[2][4];
            #pragma unroll
            for (int mi = 0; mi < 2; mi++)
                ldsm_x4(a[mi][0], a[mi][1], a[mi][2], a[mi][3], qa[mi] + koff);
            uint32_t b[4][4];
            #pragma unroll
            for (int p = 0; p < 4; p++)
                ldsm_x4(b[p][0], b[p][1], b[p][2], b[p][3], kb[p] + koff);
            #pragma unroll
            for (int mi = 0; mi < 2; mi++)
                #pragma unroll
                for (int ni = 0; ni < 8; ni++) {
                    int p = ni >> 1, hi = (ni & 1) << 1;
                    mma_tf32u(acc[mi][ni][0], acc[mi][ni][1], acc[mi][ni][2], acc[mi][ni][3],
                              a[mi][0], a[mi][1], a[mi][2], a[mi][3],
                              b[p][hi], b[p][hi + 1]);
                }
        }

        #pragma unroll
        for (int mi = 0; mi < 2; mi++)
            #pragma unroll
            for (int ni = 0; ni < 8; ni++) {
                rp[mi][0] += __expf(scale * acc[mi][ni][0]) + __expf(scale * acc[mi][ni][1]);
                rp[mi][1] += __expf(scale * acc[mi][ni][2]) + __expf(scale * acc[mi][ni][3]);
            }
    }

    #pragma unroll
    for (int mi = 0; mi < 2; mi++)
        #pragma unroll
        for (int hh = 0; hh < 2; hh++) {
            rp[mi][hh] += __shfl_xor_sync(0xffffffffu, rp[mi][hh], 1);
            rp[mi][hh] += __shfl_xor_sync(0xffffffffu, rp[mi][hh], 2);
        }
    if (tig == 0) {
        #pragma unroll
        for (int mi = 0; mi < 2; mi++)
            #pragma unroll
            for (int hh = 0; hh < 2; hh++)
                red[wn][wm0 + mi * 16 + gid + 8 * hh] = rp[mi][hh];
    }
    __syncthreads();
    if (tid < 128) {
        long row = (long)h * S_LEN + mb * 128 + tid;
        inv[row] = 1.0f / (red[0][tid] + red[1][tid]);
    }
}

// ---------------------------------------------------------------------------
// Fused attention (inputs already tf32 -> plain copies; LDSM on Qs/Ks/Ps).
// ---------------------------------------------------------------------------
__global__ void __launch_bounds__(256, 2)
fused_attn_kernel(const float* __restrict__ Qp, const float* __restrict__ Kp,
                  const float* __restrict__ Vp, const float* __restrict__ invp,
                  float* __restrict__ attn, float* __restrict__ vals, float scale)
{
    extern __shared__ __align__(16) float sm[];
    const int LD = D_HEAD + 4;
    float (*Qs)[D_HEAD + 4] = (float (*)[D_HEAD + 4])sm;
    float (*Ks)[D_HEAD + 4] = (float (*)[D_HEAD + 4])(sm + 128 * LD);
    float (*Vs)[D_HEAD + 4] = (float (*)[D_HEAD + 4])(sm + 192 * LD);
    float (*Ps)[D_HEAD + 4] = (float (*)[D_HEAD + 4])(sm + 256 * LD);
    float* invs = sm + 384 * LD;

    const int mb = blockIdx.x, h = blockIdx.y;
    const float* Aq = Qp + (long)mb * 128 * D_MODEL + h * D_HEAD;
    const long attn_row0 = (long)h * S_LEN + mb * 128;

    const int tid = threadIdx.x;
    const int warp = tid >> 5;
    const int lane = tid & 31;
    const int gid = lane >> 2;
    const int tig = lane & 3;
    const int wm0 = (warp >> 1) * 32;
    const int wn0 = (warp & 1) * 32;

    const int arow = lane & 15;
    const int acol = (lane >> 4) << 2;
    const int brow = (lane & 7) + ((lane >> 4) << 3);
    const int bcol = ((lane >> 3) & 1) << 2;

    #pragma unroll
    for (int i = 0; i < 8; i++) {
        int idx = tid + i * 256;
        int r = idx >> 4;
        int c4 = (idx & 15) * 4;
        *(float4*)&Qs[r][c4] = *(const float4*)(Aq + (long)r * D_MODEL + c4);
    }
    if (tid < 128) invs[tid] = invp[attn_row0 + tid];

    uint32_t qa[2], pa[2];
    #pragma unroll
    for (int mi = 0; mi < 2; mi++) {
        qa[mi] = smem_u32(&Qs[wm0 + mi * 16 + arow][acol]);
        pa[mi] = smem_u32(&Ps[wm0 + mi * 16 + arow][acol]);
    }
    uint32_t kb[2];
    #pragma unroll
    for (int p = 0; p < 2; p++)
        kb[p] = smem_u32(&Ks[wn0 + p * 16 + brow][bcol]);

    float oacc[2][4][4];
    #pragma unroll
    for (int mi = 0; mi < 2; mi++)
        #pragma unroll
        for (int ni = 0; ni < 4; ni++)
            #pragma unroll
            for (int j = 0; j < 4; j++) oacc[mi][ni][j] = 0.f;

    for (int nb = 0; nb < S_LEN / D_HEAD; nb++) {
        __syncthreads();
        #pragma unroll
        for (int i = 0; i < 4; i++) {
            int idx = tid + i * 256;
            int r = idx >> 4;
            int c4 = (idx & 15) * 4;
            const float* gk = Kp + (long)(nb * 64 + r) * D_MODEL + h * D_HEAD + c4;
            *(float4*)&Ks[r][c4] = *(const float4*)gk;
            const float* gv = Vp + (long)(nb * 64 + r) * D_MODEL + h * D_HEAD + c4;
            *(float4*)&Vs[r][c4] = *(const float4*)gv;
        }
        __syncthreads();

        float acc[2][4][4];
        #pragma unroll
        for (int mi = 0; mi < 2; mi++)
            #pragma unroll
            for (int ni = 0; ni < 4; ni++)
                #pragma unroll
                for (int j = 0; j < 4; j++) acc[mi][ni][j] = 0.f;

        #pragma unroll
        for (int ksi = 0; ksi < 8; ksi++) {
            const uint32_t koff = ksi * 8 * 4;
            uint32_t a[2][4];
            #pragma unroll
            for (int mi = 0; mi < 2; mi++)
                ldsm_x4(a[mi][0], a[mi][1], a[mi][2], a[mi][3], qa[mi] + koff);
            uint32_t b[2][4];
            #pragma unroll
            for (int p = 0; p < 2; p++)
                ldsm_x4(b[p][0], b[p][1], b[p][2], b[p][3], kb[p] + koff);
            #pragma unroll
            for (int mi = 0; mi < 2; mi++)
                #pragma unroll
                for (int ni = 0; ni < 4; ni++) {
                    int p = ni >> 1, hi = (ni & 1) << 1;
                    mma_tf32u(acc[mi][ni][0], acc[mi][ni][1], acc[mi][ni][2], acc[mi][ni][3],
                              a[mi][0], a[mi][1], a[mi][2], a[mi][3],
                              b[p][hi], b[p][hi + 1]);
                }
        }

        #pragma unroll
        for (int mi = 0; mi < 2; mi++) {
            int r = wm0 + mi * 16 + gid;
            float iv0 = invs[r], iv1 = invs[r + 8];
            #pragma unroll
            for (int ni = 0; ni < 4; ni++) {
                int c = wn0 + ni * 8 + tig * 2;
                *(float2*)&Ps[r][c] =
                    make_float2(__expf(scale * acc[mi][ni][0]) * iv0,
                                __expf(scale * acc[mi][ni][1]) * iv0);
                *(float2*)&Ps[r + 8][c] =
                    make_float2(__expf(scale * acc[mi][ni][2]) * iv1,
                                __expf(scale * acc[mi][ni][3]) * iv1);
            }
        }
        __syncthreads();

        #pragma unroll
        for (int ksi = 0; ksi < 8; ksi++) {
            const int ks = ksi * 8;
            const uint32_t koff = ks * 4;
            uint32_t a[2][4];
            #pragma unroll
            for (int mi = 0; mi < 2; mi++)
                ldsm_x4(a[mi][0], a[mi][1], a[mi][2], a[mi][3], pa[mi] + koff);
            float bf[4][2];
            #pragma unroll
            for (int ni = 0; ni < 4; ni++) {
                bf[ni][0] = Vs[ks + tig][wn0 + ni * 8 + gid];
                bf[ni][1] = Vs[ks + tig + 4][wn0 + ni * 8 + gid];
            }
            #pragma unroll
            for (int mi = 0; mi < 2; mi++)
                #pragma unroll
                for (int ni = 0; ni < 4; ni++)
                    mma_tf32u(oacc[mi][ni][0], oacc[mi][ni][1], oacc[mi][ni][2], oacc[mi][ni][3],
                              a[mi][0], a[mi][1], a[mi][2], a[mi][3],
                              __float_as_uint(bf[ni][0]), __float_as_uint(bf[ni][1]));
        }

        #pragma unroll
        for (int i = 0; i < 8; i++) {
            int idx = tid + i * 256;
            int r = idx >> 4;
            int c4 = (idx & 15) * 4;
            *(float4*)&attn[(attn_row0 + r) * S_LEN + nb * 64 + c4] =
                *(const float4*)&Ps[r][c4];
        }
    }

    #pragma unroll
    for (int mi = 0; mi < 2; mi++) {
        int r0 = mb * 128 + wm0 + mi * 16 + gid;
        #pragma unroll
        for (int ni = 0; ni < 4; ni++) {
            int c = h * D_HEAD + wn0 + ni * 8 + tig * 2;
            *(float2*)&vals[(long)r0 * D_MODEL + c] =
                make_float2(oacc[mi][ni][0], oacc[mi][ni][1]);
            *(float2*)&vals[(long)(r0 + 8) * D_MODEL + c] =
                make_float2(oacc[mi][ni][2], oacc[mi][ni][3]);
        }
    }
}

extern "C" void kernel_launch(void* const* d_in, const int* in_sizes, int n_in,
                              void* d_out, int out_size)
{
    const float* q  = (const float*)d_in[0];
    const float* k  = (const float*)d_in[1];
    const float* v  = (const float*)d_in[2];
    const float* Wq = (const float*)d_in[3];
    const float* bq = (const float*)d_in[4];
    const float* Wk = (const float*)d_in[5];
    const float* bk = (const float*)d_in[6];
    const float* Wv = (const float*)d_in[7];
    const float* bv = (const float*)d_in[8];
    const float* Wo = (const float*)d_in[9];
    const float* bo = (const float*)d_in[10];

    float* out = (float*)d_out;

    float *Qp, *Kp, *Vp, *Vals, *Wt, *Inv, *attn_fb;
    cudaGetSymbolAddress((void**)&Qp,   g_Qp);
    cudaGetSymbolAddress((void**)&Kp,   g_Kp);
    cudaGetSymbolAddress((void**)&Vp,   g_Vp);
    cudaGetSymbolAddress((void**)&Vals, g_vals);
    cudaGetSymbolAddress((void**)&Wt,   g_Wt);
    cudaGetSymbolAddress((void**)&Inv,  g_inv);
    cudaGetSymbolAddress((void**)&attn_fb, g_attn_fallback);

    const long OUT_ELEMS  = (long)S_LEN * D_MODEL;
    const long ATTN_ELEMS = (long)N_HEADS * S_LEN * S_LEN;
    float* attn = ((long)out_size >= OUT_ELEMS + ATTN_ELEMS)
                      ? (out + OUT_ELEMS)
                      : attn_fb;

    const int LD = D_HEAD + 4;
    const int ROWSUM_SMEM = 2 * 128 * LD * (int)sizeof(float);           // ~69.6 KB
    const int FUSED_SMEM  = (384 * LD + 128) * (int)sizeof(float);       // ~105 KB
    static bool attr_done = false;
    if (!attr_done) {
        cudaFuncSetAttribute(rowsum_kernel,
                             cudaFuncAttributeMaxDynamicSharedMemorySize, ROWSUM_SMEM);
        cudaFuncSetAttribute(fused_attn_kernel,
                             cudaFuncAttributeMaxDynamicSharedMemorySize, FUSED_SMEM);
        attr_done = true;
    }

    dim3 blk(256);
    const float scale = 1.0f / sqrtf((float)D_HEAD);

    // 0) Transpose + tf32-round all four weight matrices
    transpose_w<<<dim3(32, 32, 4), dim3(32, 8)>>>(Wq, Wk, Wv, Wo, Wt);

    // 1) QKV projections (NT, dual-LDSM), outputs pre-rounded to tf32
    dim3 gQKV(D_MODEL / 128, S_LEN / 128, 3);
    qkv_proj<<<gQKV, blk>>>(q, k, v, Wt, bq, bk, bv, Qp, Kp, Vp);

    // 2) Row sums -> inv
    dim3 gRS(S_LEN / 128, N_HEADS);
    rowsum_kernel<<<gRS, blk, ROWSUM_SMEM>>>(Qp, Kp, Inv, scale);

    // 3) Fused: recompute scores, normalize, write attn once, O = P@V
    dim3 gF(S_LEN / 128, N_HEADS);
    fused_attn_kernel<<<gF, blk, FUSED_SMEM>>>(Qp, Kp, Vp, Inv, attn, Vals, scale);

    // 4) out = vals @ Wo + bo (fp32 output)
    dim3 gProj(D_MODEL / 128, S_LEN / 128, 1);
    o_proj<<<gProj, blk>>>(Vals, Wt, out, bo);
}

// round 14
// speedup vs baseline: 1.0673x; 1.0673x over previous
#include <cuda_runtime.h>
#include <math.h>
#include <stdint.h>

#define S_LEN 4096
#define D_MODEL 1024
#define N_HEADS 16
#define D_HEAD 64

// Scratch (allocation-free rule: __device__ globals)
__device__ float g_Qp[S_LEN * D_MODEL];
__device__ float g_Kp[S_LEN * D_MODEL];
__device__ float g_Vp[S_LEN * D_MODEL];
__device__ float g_vals[S_LEN * D_MODEL];
__device__ float g_Wt[4 * D_MODEL * D_MODEL];     // transposed tf32 weights
__device__ float g_inv[(size_t)N_HEADS * S_LEN];  // 1 / rowsum
__device__ float g_attn_fallback[(size_t)N_HEADS * S_LEN * S_LEN];

__device__ __forceinline__ float to_tf32(float x) {
    float y;
    asm("cvt.rna.tf32.f32 %0, %1;" : "=f"(y) : "f"(x));
    return y;
}

__device__ __forceinline__ float4 tf32_4(float4 f) {
    return make_float4(to_tf32(f.x), to_tf32(f.y), to_tf32(f.z), to_tf32(f.w));
}

__device__ __forceinline__ uint32_t smem_u32(const void* p) {
    return (uint32_t)__cvta_generic_to_shared(p);
}

__device__ __forceinline__ void cp_async16(uint32_t dst, const void* src) {
    asm volatile("cp.async.cg.shared.global [%0], [%1], 16;" :: "r"(dst), "l"(src));
}
__device__ __forceinline__ void cp_commit() {
    asm volatile("cp.async.commit_group;");
}
template <int N>
__device__ __forceinline__ void cp_wait() {
    asm volatile("cp.async.wait_group %0;" :: "n"(N));
}

__device__ __forceinline__ void ldsm_x4(uint32_t& r0, uint32_t& r1,
                                        uint32_t& r2, uint32_t& r3, uint32_t addr)
{
    asm volatile("ldmatrix.sync.aligned.m8n8.x4.shared.b16 {%0,%1,%2,%3}, [%4];"
                 : "=r"(r0), "=r"(r1), "=r"(r2), "=r"(r3) : "r"(addr));
}

__device__ __forceinline__ void mma_tf32u(float& d0, float& d1, float& d2, float& d3,
                                          uint32_t a0, uint32_t a1, uint32_t a2, uint32_t a3,
                                          uint32_t b0, uint32_t b1)
{
    asm volatile(
        "mma.sync.aligned.m16n8k8.row.col.f32.tf32.tf32.f32 "
        "{%0,%1,%2,%3}, {%4,%5,%6,%7}, {%8,%9}, {%0,%1,%2,%3};"
        : "+f"(d0), "+f"(d1), "+f"(d2), "+f"(d3)
        : "r"(a0), "r"(a1), "r"(a2), "r"(a3), "r"(b0), "r"(b1));
}

// ---------------------------------------------------------------------------
// Weight transpose: Wt[z][n][k] = tf32(W[z][k][n]).
// ---------------------------------------------------------------------------
__global__ void transpose_w(const float* __restrict__ W0, const float* __restrict__ W1,
                            const float* __restrict__ W2, const float* __restrict__ W3,
                            float* __restrict__ Wt)
{
    const float* W = (blockIdx.z == 0) ? W0 : (blockIdx.z == 1) ? W1
                   : (blockIdx.z == 2) ? W2 : W3;
    float* T = Wt + (size_t)blockIdx.z * D_MODEL * D_MODEL;
    __shared__ float t[32][33];
    int x = blockIdx.x * 32 + threadIdx.x;
    int y0 = blockIdx.y * 32;
    #pragma unroll
    for (int i = threadIdx.y; i < 32; i += 8)
        t[i][threadIdx.x] = W[(long)(y0 + i) * D_MODEL + x];
    __syncthreads();
    int xo = y0 + threadIdx.x;
    int yo0 = blockIdx.x * 32;
    #pragma unroll
    for (int i = threadIdx.y; i < 32; i += 8)
        T[(long)(yo0 + i) * D_MODEL + xo] = to_tf32(t[threadIdx.x][i]);
}

// ---------------------------------------------------------------------------
// NT projection: C = A @ Bt^T + bias (dual-LDSM).  CVT_OUT rounds outputs.
// ---------------------------------------------------------------------------
template <bool CVT_OUT>
__device__ __forceinline__ void proj_nt(const float* __restrict__ A,
                                        const float* __restrict__ Bt,
                                        float* __restrict__ C,
                                        const float* __restrict__ bias)
{
    __shared__ __align__(16) float As[128][36];
    __shared__ __align__(16) float Bs[128][36];

    const int m0 = blockIdx.y * 128;
    const int n0 = blockIdx.x * 128;
    const int tid = threadIdx.x;
    const int warp = tid >> 5;
    const int lane = tid & 31;
    const int gid = lane >> 2;
    const int tig = lane & 3;
    const int wm0 = (warp >> 1) * 32;
    const int wn0 = (warp & 1) * 64;

    const int arow = lane & 15;
    const int acol = (lane >> 4) << 2;
    const int brow = (lane & 7) + ((lane >> 4) << 3);
    const int bcol = ((lane >> 3) & 1) << 2;

    uint32_t aaddr[2];
    #pragma unroll
    for (int mi = 0; mi < 2; mi++)
        aaddr[mi] = smem_u32(&As[wm0 + mi * 16 + arow][acol]);
    uint32_t baddr[4];
    #pragma unroll
    for (int p = 0; p < 4; p++)
        baddr[p] = smem_u32(&Bs[wn0 + p * 16 + brow][bcol]);

    float acc[2][8][4];
    #pragma unroll
    for (int mi = 0; mi < 2; mi++)
        #pragma unroll
        for (int ni = 0; ni < 8; ni++)
            #pragma unroll
            for (int j = 0; j < 4; j++) acc[mi][ni][j] = 0.f;

    for (int k0 = 0; k0 < D_MODEL; k0 += 32) {
        #pragma unroll
        for (int i = 0; i < 4; i++) {
            int idx = tid + i * 256;
            int r = idx >> 3;
            int kq = (idx & 7) * 4;
            *(float4*)&As[r][kq] =
                tf32_4(*(const float4*)(A + (long)(m0 + r) * D_MODEL + k0 + kq));
            *(float4*)&Bs[r][kq] =
                *(const float4*)(Bt + (long)(n0 + r) * D_MODEL + k0 + kq);
        }
        __syncthreads();

        #pragma unroll
        for (int ksi = 0; ksi < 4; ksi++) {
            const uint32_t koff = ksi * 8 * 4;
            uint32_t a[2][4];
            #pragma unroll
            for (int mi = 0; mi < 2; mi++)
                ldsm_x4(a[mi][0], a[mi][1], a[mi][2], a[mi][3], aaddr[mi] + koff);
            uint32_t b[4][4];
            #pragma unroll
            for (int p = 0; p < 4; p++)
                ldsm_x4(b[p][0], b[p][1], b[p][2], b[p][3], baddr[p] + koff);
            #pragma unroll
            for (int mi = 0; mi < 2; mi++)
                #pragma unroll
                for (int ni = 0; ni < 8; ni++) {
                    int p = ni >> 1, hi = (ni & 1) << 1;
                    mma_tf32u(acc[mi][ni][0], acc[mi][ni][1], acc[mi][ni][2], acc[mi][ni][3],
                              a[mi][0], a[mi][1], a[mi][2], a[mi][3],
                              b[p][hi], b[p][hi + 1]);
                }
        }
        __syncthreads();
    }

    #pragma unroll
    for (int mi = 0; mi < 2; mi++) {
        int r0 = m0 + wm0 + mi * 16 + gid;
        #pragma unroll
        for (int ni = 0; ni < 8; ni++) {
            int c = n0 + wn0 + ni * 8 + tig * 2;
            float b0 = bias[c], b1 = bias[c + 1];
            float v0 = acc[mi][ni][0] + b0, v1 = acc[mi][ni][1] + b1;
            float v2 = acc[mi][ni][2] + b0, v3 = acc[mi][ni][3] + b1;
            if (CVT_OUT) {
                v0 = to_tf32(v0); v1 = to_tf32(v1);
                v2 = to_tf32(v2); v3 = to_tf32(v3);
            }
            *(float2*)&C[(long)r0 * D_MODEL + c] = make_float2(v0, v1);
            *(float2*)&C[(long)(r0 + 8) * D_MODEL + c] = make_float2(v2, v3);
        }
    }
}

__global__ void __launch_bounds__(256, 2)
qkv_proj(const float* __restrict__ q, const float* __restrict__ k,
         const float* __restrict__ v, const float* __restrict__ Wt,
         const float* __restrict__ bq, const float* __restrict__ bk,
         const float* __restrict__ bv,
         float* __restrict__ Qp, float* __restrict__ Kp, float* __restrict__ Vp)
{
    int z = blockIdx.z;
    const float* A = (z == 0) ? q : (z == 1) ? k : v;
    const float* Bt = Wt + (size_t)z * D_MODEL * D_MODEL;
    const float* bias = (z == 0) ? bq : (z == 1) ? bk : bv;
    float* C = (z == 0) ? Qp : (z == 1) ? Kp : Vp;
    proj_nt<true>(A, Bt, C, bias);
}

__global__ void __launch_bounds__(256, 2)
o_proj(const float* __restrict__ A, const float* __restrict__ Wt,
       float* __restrict__ C, const float* __restrict__ bias)
{
    proj_nt<false>(A, Wt + (size_t)3 * D_MODEL * D_MODEL, C, bias);
}

// ---------------------------------------------------------------------------
// Rowsum pass: double-buffered K via cp.async; copy overlaps mma+exp.
// Smem: Qs[128][68] + Ks[2][128][68] = ~102 KB (occ 2).
// ---------------------------------------------------------------------------
__global__ void __launch_bounds__(256, 2)
rowsum_kernel(const float* __restrict__ Qp, const float* __restrict__ Kp,
              float* __restrict__ inv, float scale)
{
    extern __shared__ __align__(16) float sm[];
    const int LD = D_HEAD + 4;
    float (*Qs)[D_HEAD + 4] = (float (*)[D_HEAD + 4])sm;
    float (*Ks)[128][D_HEAD + 4] = (float (*)[128][D_HEAD + 4])(sm + 128 * LD);
    __shared__ float red[2][128];

    const int mb = blockIdx.x, h = blockIdx.y;
    const float* Aq = Qp + (long)mb * 128 * D_MODEL + h * D_HEAD;
    const float* Kg = Kp + h * D_HEAD;

    const int tid = threadIdx.x;
    const int warp = tid >> 5;
    const int lane = tid & 31;
    const int gid = lane >> 2;
    const int tig = lane & 3;
    const int wm0 = (warp >> 1) * 32;
    const int wn = warp & 1;
    const int wn0 = wn * 64;

    const int arow = lane & 15;
    const int acol = (lane >> 4) << 2;
    const int brow = (lane & 7) + ((lane >> 4) << 3);
    const int bcol = ((lane >> 3) & 1) << 2;

    // prologue: cp.async K tile 0, stage Q meanwhile
    #pragma unroll
    for (int i = 0; i < 8; i++) {
        int idx = tid + i * 256;
        int r = idx >> 4;
        int c4 = (idx & 15) * 4;
        cp_async16(smem_u32(&Ks[0][r][c4]), Kg + (long)r * D_MODEL + c4);
    }
    cp_commit();
    #pragma unroll
    for (int i = 0; i < 8; i++) {
        int idx = tid + i * 256;
        int r = idx >> 4;
        int c4 = (idx & 15) * 4;
        *(float4*)&Qs[r][c4] = *(const float4*)(Aq + (long)r * D_MODEL + c4);
    }

    uint32_t qa[2];
    #pragma unroll
    for (int mi = 0; mi < 2; mi++)
        qa[mi] = smem_u32(&Qs[wm0 + mi * 16 + arow][acol]);
    uint32_t kb[2][4];
    #pragma unroll
    for (int bufi = 0; bufi < 2; bufi++)
        #pragma unroll
        for (int p = 0; p < 4; p++)
            kb[bufi][p] = smem_u32(&Ks[bufi][wn0 + p * 16 + brow][bcol]);

    cp_wait<0>();
    __syncthreads();

    float rp[2][2] = {{0.f, 0.f}, {0.f, 0.f}};

    for (int nb = 0; nb < S_LEN / 128; nb++) {
        const int cur = nb & 1, nxt = cur ^ 1;
        // prefetch next tile into the other buffer (overlaps mma + exp)
        if (nb + 1 < S_LEN / 128) {
            const float* Bk = Kg + (long)(nb + 1) * 128 * D_MODEL;
            #pragma unroll
            for (int i = 0; i < 8; i++) {
                int idx = tid + i * 256;
                int r = idx >> 4;
                int c4 = (idx & 15) * 4;
                cp_async16(smem_u32(&Ks[nxt][r][c4]), Bk + (long)r * D_MODEL + c4);
            }
        }
        cp_commit();

        float acc[2][8][4];
        #pragma unroll
        for (int mi = 0; mi < 2; mi++)
            #pragma unroll
            for (int ni = 0; ni < 8; ni++)
                #pragma unroll
                for (int j = 0; j < 4; j++) acc[mi][ni][j] = 0.f;

        #pragma unroll
        for (int ksi = 0; ksi < 8; ksi++) {
            const uint32_t koff = ksi * 8 * 4;
            uint32_t a[2][4];
            #pragma unroll
            for (int mi = 0; mi < 2; mi++)
                ldsm_x4(a[mi][0], a[mi][1], a[mi][2], a[mi][3], qa[mi] + koff);
            uint32_t b[4][4];
            #pragma unroll
            for (int p = 0; p < 4; p++)
                ldsm_x4(b[p][0], b[p][1], b[p][2], b[p][3], kb[cur][p] + koff);
            #pragma unroll
            for (int mi = 0; mi < 2; mi++)
                #pragma unroll
                for (int ni = 0; ni < 8; ni++) {
                    int p = ni >> 1, hi = (ni & 1) << 1;
                    mma_tf32u(acc[mi][ni][0], acc[mi][ni][1], acc[mi][ni][2], acc[mi][ni][3],
                              a[mi][0], a[mi][1], a[mi][2], a[mi][3],
                              b[p][hi], b[p][hi + 1]);
                }
        }

        #pragma unroll
        for (int mi = 0; mi < 2; mi++)
            #pragma unroll
            for (int ni = 0; ni < 8; ni++) {
                rp[mi][0] += __expf(scale * acc[mi][ni][0]) + __expf(scale * acc[mi][ni][1]);
                rp[mi][1] += __expf(scale * acc[mi][ni][2]) + __expf(scale * acc[mi][ni][3]);
            }

        cp_wait<0>();
        __syncthreads();
    }

    #pragma unroll
    for (int mi = 0; mi < 2; mi++)
        #pragma unroll
        for (int hh = 0; hh < 2; hh++) {
            rp[mi][hh] += __shfl_xor_sync(0xffffffffu, rp[mi][hh], 1);
            rp[mi][hh] += __shfl_xor_sync(0xffffffffu, rp[mi][hh], 2);
        }
    if (tig == 0) {
        #pragma unroll
        for (int mi = 0; mi < 2; mi++)
            #pragma unroll
            for (int hh = 0; hh < 2; hh++)
                red[wn][wm0 + mi * 16 + gid + 8 * hh] = rp[mi][hh];
    }
    __syncthreads();
    if (tid < 128) {
        long row = (long)h * S_LEN + mb * 128 + tid;
        inv[row] = 1.0f / (red[0][tid] + red[1][tid]);
    }
}

// ---------------------------------------------------------------------------
// Fused attention: single-buffer cp.async liveness pipeline.
//   K(nb+1) copy overlaps PV + attn store; V(nb+1) copy overlaps next S + exp.
// ---------------------------------------------------------------------------
__global__ void __launch_bounds__(256, 2)
fused_attn_kernel(const float* __restrict__ Qp, const float* __restrict__ Kp,
                  const float* __restrict__ Vp, const float* __restrict__ invp,
                  float* __restrict__ attn, float* __restrict__ vals, float scale)
{
    extern __shared__ __align__(16) float sm[];
    const int LD = D_HEAD + 4;
    float (*Qs)[D_HEAD + 4] = (float (*)[D_HEAD + 4])sm;
    float (*Ks)[D_HEAD + 4] = (float (*)[D_HEAD + 4])(sm + 128 * LD);
    float (*Vs)[D_HEAD + 4] = (float (*)[D_HEAD + 4])(sm + 192 * LD);
    float (*Ps)[D_HEAD + 4] = (float (*)[D_HEAD + 4])(sm + 256 * LD);
    float* invs = sm + 384 * LD;

    const int mb = blockIdx.x, h = blockIdx.y;
    const float* Aq = Qp + (long)mb * 128 * D_MODEL + h * D_HEAD;
    const float* Kg = Kp + h * D_HEAD;
    const float* Vg = Vp + h * D_HEAD;
    const long attn_row0 = (long)h * S_LEN + mb * 128;

    const int tid = threadIdx.x;
    const int warp = tid >> 5;
    const int lane = tid & 31;
    const int gid = lane >> 2;
    const int tig = lane & 3;
    const int wm0 = (warp >> 1) * 32;
    const int wn0 = (warp & 1) * 32;

    const int arow = lane & 15;
    const int acol = (lane >> 4) << 2;
    const int brow = (lane & 7) + ((lane >> 4) << 3);
    const int bcol = ((lane >> 3) & 1) << 2;

    // prologue: async K0, V0; stage Q + inv meanwhile
    #pragma unroll
    for (int i = 0; i < 4; i++) {
        int idx = tid + i * 256;
        int r = idx >> 4;
        int c4 = (idx & 15) * 4;
        cp_async16(smem_u32(&Ks[r][c4]), Kg + (long)r * D_MODEL + c4);
    }
    cp_commit();
    #pragma unroll
    for (int i = 0; i < 4; i++) {
        int idx = tid + i * 256;
        int r = idx >> 4;
        int c4 = (idx & 15) * 4;
        cp_async16(smem_u32(&Vs[r][c4]), Vg + (long)r * D_MODEL + c4);
    }
    cp_commit();

    #pragma unroll
    for (int i = 0; i < 8; i++) {
        int idx = tid + i * 256;
        int r = idx >> 4;
        int c4 = (idx & 15) * 4;
        *(float4*)&Qs[r][c4] = *(const float4*)(Aq + (long)r * D_MODEL + c4);
    }
    if (tid < 128) invs[tid] = invp[attn_row0 + tid];

    uint32_t qa[2], pa[2];
    #pragma unroll
    for (int mi = 0; mi < 2; mi++) {
        qa[mi] = smem_u32(&Qs[wm0 + mi * 16 + arow][acol]);
        pa[mi] = smem_u32(&Ps[wm0 + mi * 16 + arow][acol]);
    }
    uint32_t kb[2];
    #pragma unroll
    for (int p = 0; p < 2; p++)
        kb[p] = smem_u32(&Ks[wn0 + p * 16 + brow][bcol]);

    float oacc[2][4][4];
    #pragma unroll
    for (int mi = 0; mi < 2; mi++)
        #pragma unroll
        for (int ni = 0; ni < 4; ni++)
            #pragma unroll
            for (int j = 0; j < 4; j++) oacc[mi][ni][j] = 0.f;

    cp_wait<0>();
    __syncthreads();

    for (int nb = 0; nb < S_LEN / D_HEAD; nb++) {
        // ---- S = Q @ K^T ----
        float acc[2][4][4];
        #pragma unroll
        for (int mi = 0; mi < 2; mi++)
            #pragma unroll
            for (int ni = 0; ni < 4; ni++)
                #pragma unroll
                for (int j = 0; j < 4; j++) acc[mi][ni][j] = 0.f;

        #pragma unroll
        for (int ksi = 0; ksi < 8; ksi++) {
            const uint32_t koff = ksi * 8 * 4;
            uint32_t a[2][4];
            #pragma unroll
            for (int mi = 0; mi < 2; mi++)
                ldsm_x4(a[mi][0], a[mi][1], a[mi][2], a[mi][3], qa[mi] + koff);
            uint32_t b[2][4];
            #pragma unroll
            for (int p = 0; p < 2; p++)
                ldsm_x4(b[p][0], b[p][1], b[p][2], b[p][3], kb[p] + koff);
            #pragma unroll
            for (int mi = 0; mi < 2; mi++)
                #pragma unroll
                for (int ni = 0; ni < 4; ni++) {
                    int p = ni >> 1, hi = (ni & 1) << 1;
                    mma_tf32u(acc[mi][ni][0], acc[mi][ni][1], acc[mi][ni][2], acc[mi][ni][3],
                              a[mi][0], a[mi][1], a[mi][2], a[mi][3],
                              b[p][hi], b[p][hi + 1]);
                }
        }

        // ---- p = exp(scale*s) * inv -> Ps ----
        #pragma unroll
        for (int mi = 0; mi < 2; mi++) {
            int r = wm0 + mi * 16 + gid;
            float iv0 = invs[r], iv1 = invs[r + 8];
            #pragma unroll
            for (int ni = 0; ni < 4; ni++) {
                int c = wn0 + ni * 8 + tig * 2;
                *(float2*)&Ps[r][c] =
                    make_float2(__expf(scale * acc[mi][ni][0]) * iv0,
                                __expf(scale * acc[mi][ni][1]) * iv0);
                *(float2*)&Ps[r + 8][c] =
                    make_float2(__expf(scale * acc[mi][ni][2]) * iv1,
                                __expf(scale * acc[mi][ni][3]) * iv1);
            }
        }

        cp_wait<0>();        // V(nb) complete (committed last iteration)
        __syncthreads();     // Ps ready; Vs visible; Ks fully consumed

        // ---- prefetch K(nb+1) into Ks (overlaps PV + attn store) ----
        if (nb + 1 < S_LEN / D_HEAD) {
            const float* gk = Kg + (long)(nb + 1) * 64 * D_MODEL;
            #pragma unroll
            for (int i = 0; i < 4; i++) {
                int idx = tid + i * 256;
                int r = idx >> 4;
                int c4 = (idx & 15) * 4;
                cp_async16(smem_u32(&Ks[r][c4]), gk + (long)r * D_MODEL + c4);
            }
        }
        cp_commit();

        // ---- O += Ps @ Vs ----
        #pragma unroll
        for (int ksi = 0; ksi < 8; ksi++) {
            const int ks = ksi * 8;
            const uint32_t koff = ks * 4;
            uint32_t a[2][4];
            #pragma unroll
            for (int mi = 0; mi < 2; mi++)
                ldsm_x4(a[mi][0], a[mi][1], a[mi][2], a[mi][3], pa[mi] + koff);
            float bf[4][2];
            #pragma unroll
            for (int ni = 0; ni < 4; ni++) {
                bf[ni][0] = Vs[ks + tig][wn0 + ni * 8 + gid];
                bf[ni][1] = Vs[ks + tig + 4][wn0 + ni * 8 + gid];
            }
            #pragma unroll
            for (int mi = 0; mi < 2; mi++)
                #pragma unroll
                for (int ni = 0; ni < 4; ni++)
                    mma_tf32u(oacc[mi][ni][0], oacc[mi][ni][1], oacc[mi][ni][2], oacc[mi][ni][3],
                              a[mi][0], a[mi][1], a[mi][2], a[mi][3],
                              __float_as_uint(bf[ni][0]), __float_as_uint(bf[ni][1]));
        }

        // ---- attn tile write from Ps (coalesced float4) ----
        #pragma unroll
        for (int i = 0; i < 8; i++) {
            int idx = tid + i * 256;
            int r = idx >> 4;
            int c4 = (idx & 15) * 4;
            *(float4*)&attn[(attn_row0 + r) * S_LEN + nb * 64 + c4] =
                *(const float4*)&Ps[r][c4];
        }

        __syncthreads();     // Vs and Ps fully consumed by all warps

        // ---- prefetch V(nb+1) into Vs (overlaps next S + exp) ----
        if (nb + 1 < S_LEN / D_HEAD) {
            const float* gv = Vg + (long)(nb + 1) * 64 * D_MODEL;
            #pragma unroll
            for (int i = 0; i < 4; i++) {
                int idx = tid + i * 256;
                int r = idx >> 4;
                int c4 = (idx & 15) * 4;
                cp_async16(smem_u32(&Vs[r][c4]), gv + (long)r * D_MODEL + c4);
            }
        }
        cp_commit();

        cp_wait<1>();        // K(nb+1) done (V(nb+1) may still be in flight)
        __syncthreads();     // K visible to all before next S-mma
    }

    // Epilogue: write O
    #pragma unroll
    for (int mi = 0; mi < 2; mi++) {
        int r0 = mb * 128 + wm0 + mi * 16 + gid;
        #pragma unroll
        for (int ni = 0; ni < 4; ni++) {
            int c = h * D_HEAD + wn0 + ni * 8 + tig * 2;
            *(float2*)&vals[(long)r0 * D_MODEL + c] =
                make_float2(oacc[mi][ni][0], oacc[mi][ni][1]);
            *(float2*)&vals[(long)(r0 + 8) * D_MODEL + c] =
                make_float2(oacc[mi][ni][2], oacc[mi][ni][3]);
        }
    }
}

extern "C" void kernel_launch(void* const* d_in, const int* in_sizes, int n_in,
                              void* d_out, int out_size)
{
    const float* q  = (const float*)d_in[0];
    const float* k  = (const float*)d_in[1];
    const float* v  = (const float*)d_in[2];
    const float* Wq = (const float*)d_in[3];
    const float* bq = (const float*)d_in[4];
    const float* Wk = (const float*)d_in[5];
    const float* bk = (const float*)d_in[6];
    const float* Wv = (const float*)d_in[7];
    const float* bv = (const float*)d_in[8];
    const float* Wo = (const float*)d_in[9];
    const float* bo = (const float*)d_in[10];

    float* out = (float*)d_out;

    float *Qp, *Kp, *Vp, *Vals, *Wt, *Inv, *attn_fb;
    cudaGetSymbolAddress((void**)&Qp,   g_Qp);
    cudaGetSymbolAddress((void**)&Kp,   g_Kp);
    cudaGetSymbolAddress((void**)&Vp,   g_Vp);
    cudaGetSymbolAddress((void**)&Vals, g_vals);
    cudaGetSymbolAddress((void**)&Wt,   g_Wt);
    cudaGetSymbolAddress((void**)&Inv,  g_inv);
    cudaGetSymbolAddress((void**)&attn_fb, g_attn_fallback);

    const long OUT_ELEMS  = (long)S_LEN * D_MODEL;
    const long ATTN_ELEMS = (long)N_HEADS * S_LEN * S_LEN;
    float* attn = ((long)out_size >= OUT_ELEMS + ATTN_ELEMS)
                      ? (out + OUT_ELEMS)
                      : attn_fb;

    const int LD = D_HEAD + 4;
    const int ROWSUM_SMEM = 3 * 128 * LD * (int)sizeof(float);           // ~102 KB
    const int FUSED_SMEM  = (384 * LD + 128) * (int)sizeof(float);       // ~105 KB
    static bool attr_done = false;
    if (!attr_done) {
        cudaFuncSetAttribute(rowsum_kernel,
                             cudaFuncAttributeMaxDynamicSharedMemorySize, ROWSUM_SMEM);
        cudaFuncSetAttribute(fused_attn_kernel,
                             cudaFuncAttributeMaxDynamicSharedMemorySize, FUSED_SMEM);
        attr_done = true;
    }

    dim3 blk(256);
    const float scale = 1.0f / sqrtf((float)D_HEAD);

    // 0) Transpose + tf32-round all four weight matrices
    transpose_w<<<dim3(32, 32, 4), dim3(32, 8)>>>(Wq, Wk, Wv, Wo, Wt);

    // 1) QKV projections (NT, dual-LDSM), outputs pre-rounded to tf32
    dim3 gQKV(D_MODEL / 128, S_LEN / 128, 3);
    qkv_proj<<<gQKV, blk>>>(q, k, v, Wt, bq, bk, bv, Qp, Kp, Vp);

    // 2) Row sums -> inv (double-buffered cp.async)
    dim3 gRS(S_LEN / 128, N_HEADS);
    rowsum_kernel<<<gRS, blk, ROWSUM_SMEM>>>(Qp, Kp, Inv, scale);

    // 3) Fused: recompute scores, normalize, write attn once, O = P@V
    dim3 gF(S_LEN / 128, N_HEADS);
    fused_attn_kernel<<<gF, blk, FUSED_SMEM>>>(Qp, Kp, Vp, Inv, attn, Vals, scale);

    // 4) out = vals @ Wo + bo (fp32 output)
    dim3 gProj(D_MODEL / 128, S_LEN / 128, 1);
    o_proj<<<gProj, blk>>>(Vals, Wt, out, bo);
}

// round 16
// speedup vs baseline: 1.0779x; 1.0100x over previous
#include <cuda_runtime.h>
#include <math.h>
#include <stdint.h>

#define S_LEN 4096
#define D_MODEL 1024
#define N_HEADS 16
#define D_HEAD 64

// Scratch (allocation-free rule: __device__ globals)
__device__ float g_Qp[S_LEN * D_MODEL];
__device__ float g_Kp[S_LEN * D_MODEL];
__device__ float g_Vp[S_LEN * D_MODEL];
__device__ float g_Vt[S_LEN * D_MODEL];           // per-head transposed V
__device__ float g_vals[S_LEN * D_MODEL];
__device__ float g_Wt[4 * D_MODEL * D_MODEL];     // transposed tf32 weights
__device__ float g_inv[(size_t)N_HEADS * S_LEN];  // 1 / rowsum
__device__ float g_attn_fallback[(size_t)N_HEADS * S_LEN * S_LEN];

__device__ __forceinline__ float to_tf32(float x) {
    float y;
    asm("cvt.rna.tf32.f32 %0, %1;" : "=f"(y) : "f"(x));
    return y;
}

__device__ __forceinline__ float4 tf32_4(float4 f) {
    return make_float4(to_tf32(f.x), to_tf32(f.y), to_tf32(f.z), to_tf32(f.w));
}

__device__ __forceinline__ uint32_t smem_u32(const void* p) {
    return (uint32_t)__cvta_generic_to_shared(p);
}

__device__ __forceinline__ void cp_async16(uint32_t dst, const void* src) {
    asm volatile("cp.async.cg.shared.global [%0], [%1], 16;" :: "r"(dst), "l"(src));
}
__device__ __forceinline__ void cp_commit() {
    asm volatile("cp.async.commit_group;");
}
template <int N>
__device__ __forceinline__ void cp_wait() {
    asm volatile("cp.async.wait_group %0;" :: "n"(N));
}

__device__ __forceinline__ void ldsm_x4(uint32_t& r0, uint32_t& r1,
                                        uint32_t& r2, uint32_t& r3, uint32_t addr)
{
    asm volatile("ldmatrix.sync.aligned.m8n8.x4.shared.b16 {%0,%1,%2,%3}, [%4];"
                 : "=r"(r0), "=r"(r1), "=r"(r2), "=r"(r3) : "r"(addr));
}

__device__ __forceinline__ void mma_tf32u(float& d0, float& d1, float& d2, float& d3,
                                          uint32_t a0, uint32_t a1, uint32_t a2, uint32_t a3,
                                          uint32_t b0, uint32_t b1)
{
    asm volatile(
        "mma.sync.aligned.m16n8k8.row.col.f32.tf32.tf32.f32 "
        "{%0,%1,%2,%3}, {%4,%5,%6,%7}, {%8,%9}, {%0,%1,%2,%3};"
        : "+f"(d0), "+f"(d1), "+f"(d2), "+f"(d3)
        : "r"(a0), "r"(a1), "r"(a2), "r"(a3), "r"(b0), "r"(b1));
}

// ---------------------------------------------------------------------------
// Weight transpose: Wt[z][n][k] = tf32(W[z][k][n]).
// ---------------------------------------------------------------------------
__global__ void transpose_w(const float* __restrict__ W0, const float* __restrict__ W1,
                            const float* __restrict__ W2, const float* __restrict__ W3,
                            float* __restrict__ Wt)
{
    const float* W = (blockIdx.z == 0) ? W0 : (blockIdx.z == 1) ? W1
                   : (blockIdx.z == 2) ? W2 : W3;
    float* T = Wt + (size_t)blockIdx.z * D_MODEL * D_MODEL;
    __shared__ float t[32][33];
    int x = blockIdx.x * 32 + threadIdx.x;
    int y0 = blockIdx.y * 32;
    #pragma unroll
    for (int i = threadIdx.y; i < 32; i += 8)
        t[i][threadIdx.x] = W[(long)(y0 + i) * D_MODEL + x];
    __syncthreads();
    int xo = y0 + threadIdx.x;
    int yo0 = blockIdx.x * 32;
    #pragma unroll
    for (int i = threadIdx.y; i < 32; i += 8)
        T[(long)(yo0 + i) * D_MODEL + xo] = to_tf32(t[threadIdx.x][i]);
}

// ---------------------------------------------------------------------------
// V transpose per head: Vt[h][d][s] = Vp[s][h*64+d]. grid (128, 2, 16), blk (32,8)
// ---------------------------------------------------------------------------
__global__ void transpose_v(const float* __restrict__ Vp, float* __restrict__ Vt)
{
    __shared__ float t[32][33];
    int h = blockIdx.z;
    int s0 = blockIdx.x * 32;
    int d0 = blockIdx.y * 32;
    #pragma unroll
    for (int i = threadIdx.y; i < 32; i += 8)
        t[i][threadIdx.x] = Vp[(long)(s0 + i) * D_MODEL + h * D_HEAD + d0 + threadIdx.x];
    __syncthreads();
    float* T = Vt + (size_t)h * D_HEAD * S_LEN;
    #pragma unroll
    for (int i = threadIdx.y; i < 32; i += 8)
        T[(long)(d0 + i) * S_LEN + s0 + threadIdx.x] = t[threadIdx.x][i];
}

// ---------------------------------------------------------------------------
// NT projection: C = A @ Bt^T + bias (dual-LDSM).  CVT_OUT rounds outputs.
// ---------------------------------------------------------------------------
template <bool CVT_OUT>
__device__ __forceinline__ void proj_nt(const float* __restrict__ A,
                                        const float* __restrict__ Bt,
                                        float* __restrict__ C,
                                        const float* __restrict__ bias)
{
    __shared__ __align__(16) float As[128][36];
    __shared__ __align__(16) float Bs[128][36];

    const int m0 = blockIdx.y * 128;
    const int n0 = blockIdx.x * 128;
    const int tid = threadIdx.x;
    const int warp = tid >> 5;
    const int lane = tid & 31;
    const int gid = lane >> 2;
    const int tig = lane & 3;
    const int wm0 = (warp >> 1) * 32;
    const int wn0 = (warp & 1) * 64;

    const int arow = lane & 15;
    const int acol = (lane >> 4) << 2;
    const int brow = (lane & 7) + ((lane >> 4) << 3);
    const int bcol = ((lane >> 3) & 1) << 2;

    uint32_t aaddr[2];
    #pragma unroll
    for (int mi = 0; mi < 2; mi++)
        aaddr[mi] = smem_u32(&As[wm0 + mi * 16 + arow][acol]);
    uint32_t baddr[4];
    #pragma unroll
    for (int p = 0; p < 4; p++)
        baddr[p] = smem_u32(&Bs[wn0 + p * 16 + brow][bcol]);

    float acc[2][8][4];
    #pragma unroll
    for (int mi = 0; mi < 2; mi++)
        #pragma unroll
        for (int ni = 0; ni < 8; ni++)
            #pragma unroll
            for (int j = 0; j < 4; j++) acc[mi][ni][j] = 0.f;

    for (int k0 = 0; k0 < D_MODEL; k0 += 32) {
        #pragma unroll
        for (int i = 0; i < 4; i++) {
            int idx = tid + i * 256;
            int r = idx >> 3;
            int kq = (idx & 7) * 4;
            *(float4*)&As[r][kq] =
                tf32_4(*(const float4*)(A + (long)(m0 + r) * D_MODEL + k0 + kq));
            *(float4*)&Bs[r][kq] =
                *(const float4*)(Bt + (long)(n0 + r) * D_MODEL + k0 + kq);
        }
        __syncthreads();

        #pragma unroll
        for (int ksi = 0; ksi < 4; ksi++) {
            const uint32_t koff = ksi * 8 * 4;
            uint32_t a[2][4];
            #pragma unroll
            for (int mi = 0; mi < 2; mi++)
                ldsm_x4(a[mi][0], a[mi][1], a[mi][2], a[mi][3], aaddr[mi] + koff);
            uint32_t b[4][4];
            #pragma unroll
            for (int p = 0; p < 4; p++)
                ldsm_x4(b[p][0], b[p][1], b[p][2], b[p][3], baddr[p] + koff);
            #pragma unroll
            for (int mi = 0; mi < 2; mi++)
                #pragma unroll
                for (int ni = 0; ni < 8; ni++) {
                    int p = ni >> 1, hi = (ni & 1) << 1;
                    mma_tf32u(acc[mi][ni][0], acc[mi][ni][1], acc[mi][ni][2], acc[mi][ni][3],
                              a[mi][0], a[mi][1], a[mi][2], a[mi][3],
                              b[p][hi], b[p][hi + 1]);
                }
        }
        __syncthreads();
    }

    #pragma unroll
    for (int mi = 0; mi < 2; mi++) {
        int r0 = m0 + wm0 + mi * 16 + gid;
        #pragma unroll
        for (int ni = 0; ni < 8; ni++) {
            int c = n0 + wn0 + ni * 8 + tig * 2;
            float b0 = bias[c], b1 = bias[c + 1];
            float v0 = acc[mi][ni][0] + b0, v1 = acc[mi][ni][1] + b1;
            float v2 = acc[mi][ni][2] + b0, v3 = acc[mi][ni][3] + b1;
            if (CVT_OUT) {
                v0 = to_tf32(v0); v1 = to_tf32(v1);
                v2 = to_tf32(v2); v3 = to_tf32(v3);
            }
            *(float2*)&C[(long)r0 * D_MODEL + c] = make_float2(v0, v1);
            *(float2*)&C[(long)(r0 + 8) * D_MODEL + c] = make_float2(v2, v3);
        }
    }
}

__global__ void __launch_bounds__(256, 2)
qkv_proj(const float* __restrict__ q, const float* __restrict__ k,
         const float* __restrict__ v, const float* __restrict__ Wt,
         const float* __restrict__ bq, const float* __restrict__ bk,
         const float* __restrict__ bv,
         float* __restrict__ Qp, float* __restrict__ Kp, float* __restrict__ Vp)
{
    int z = blockIdx.z;
    const float* A = (z == 0) ? q : (z == 1) ? k : v;
    const float* Bt = Wt + (size_t)z * D_MODEL * D_MODEL;
    const float* bias = (z == 0) ? bq : (z == 1) ? bk : bv;
    float* C = (z == 0) ? Qp : (z == 1) ? Kp : Vp;
    proj_nt<true>(A, Bt, C, bias);
}

__global__ void __launch_bounds__(256, 2)
o_proj(const float* __restrict__ A, const float* __restrict__ Wt,
       float* __restrict__ C, const float* __restrict__ bias)
{
    proj_nt<false>(A, Wt + (size_t)3 * D_MODEL * D_MODEL, C, bias);
}

// ---------------------------------------------------------------------------
// Rowsum pass: double-buffered K via cp.async (unchanged from round 14).
// ---------------------------------------------------------------------------
__global__ void __launch_bounds__(256, 2)
rowsum_kernel(const float* __restrict__ Qp, const float* __restrict__ Kp,
              float* __restrict__ inv, float scale)
{
    extern __shared__ __align__(16) float sm[];
    const int LD = D_HEAD + 4;
    float (*Qs)[D_HEAD + 4] = (float (*)[D_HEAD + 4])sm;
    float (*Ks)[128][D_HEAD + 4] = (float (*)[128][D_HEAD + 4])(sm + 128 * LD);
    __shared__ float red[2][128];

    const int mb = blockIdx.x, h = blockIdx.y;
    const float* Aq = Qp + (long)mb * 128 * D_MODEL + h * D_HEAD;
    const float* Kg = Kp + h * D_HEAD;

    const int tid = threadIdx.x;
    const int warp = tid >> 5;
    const int lane = tid & 31;
    const int gid = lane >> 2;
    const int tig = lane & 3;
    const int wm0 = (warp >> 1) * 32;
    const int wn = warp & 1;
    const int wn0 = wn * 64;

    const int arow = lane & 15;
    const int acol = (lane >> 4) << 2;
    const int brow = (lane & 7) + ((lane >> 4) << 3);
    const int bcol = ((lane >> 3) & 1) << 2;

    #pragma unroll
    for (int i = 0; i < 8; i++) {
        int idx = tid + i * 256;
        int r = idx >> 4;
        int c4 = (idx & 15) * 4;
        cp_async16(smem_u32(&Ks[0][r][c4]), Kg + (long)r * D_MODEL + c4);
    }
    cp_commit();
    #pragma unroll
    for (int i = 0; i < 8; i++) {
        int idx = tid + i * 256;
        int r = idx >> 4;
        int c4 = (idx & 15) * 4;
        *(float4*)&Qs[r][c4] = *(const float4*)(Aq + (long)r * D_MODEL + c4);
    }

    uint32_t qa[2];
    #pragma unroll
    for (int mi = 0; mi < 2; mi++)
        qa[mi] = smem_u32(&Qs[wm0 + mi * 16 + arow][acol]);
    uint32_t kb[2][4];
    #pragma unroll
    for (int bufi = 0; bufi < 2; bufi++)
        #pragma unroll
        for (int p = 0; p < 4; p++)
            kb[bufi][p] = smem_u32(&Ks[bufi][wn0 + p * 16 + brow][bcol]);

    cp_wait<0>();
    __syncthreads();

    float rp[2][2] = {{0.f, 0.f}, {0.f, 0.f}};

    for (int nb = 0; nb < S_LEN / 128; nb++) {
        const int cur = nb & 1, nxt = cur ^ 1;
        if (nb + 1 < S_LEN / 128) {
            const float* Bk = Kg + (long)(nb + 1) * 128 * D_MODEL;
            #pragma unroll
            for (int i = 0; i < 8; i++) {
                int idx = tid + i * 256;
                int r = idx >> 4;
                int c4 = (idx & 15) * 4;
                cp_async16(smem_u32(&Ks[nxt][r][c4]), Bk + (long)r * D_MODEL + c4);
            }
        }
        cp_commit();

        float acc[2][8][4];
        #pragma unroll
        for (int mi = 0; mi < 2; mi++)
            #pragma unroll
            for (int ni = 0; ni < 8; ni++)
                #pragma unroll
                for (int j = 0; j < 4; j++) acc[mi][ni][j] = 0.f;

        #pragma unroll
        for (int ksi = 0; ksi < 8; ksi++) {
            const uint32_t koff = ksi * 8 * 4;
            uint32_t a[2][4];
            #pragma unroll
            for (int mi = 0; mi < 2; mi++)
                ldsm_x4(a[mi][0], a[mi][1], a[mi][2], a[mi][3], qa[mi] + koff);
            uint32_t b[4][4];
            #pragma unroll
            for (int p = 0; p < 4; p++)
                ldsm_x4(b[p][0], b[p][1], b[p][2], b[p][3], kb[cur][p] + koff);
            #pragma unroll
            for (int mi = 0; mi < 2; mi++)
                #pragma unroll
                for (int ni = 0; ni < 8; ni++) {
                    int p = ni >> 1, hi = (ni & 1) << 1;
                    mma_tf32u(acc[mi][ni][0], acc[mi][ni][1], acc[mi][ni][2], acc[mi][ni][3],
                              a[mi][0], a[mi][1], a[mi][2], a[mi][3],
                              b[p][hi], b[p][hi + 1]);
                }
        }

        #pragma unroll
        for (int mi = 0; mi < 2; mi++)
            #pragma unroll
            for (int ni = 0; ni < 8; ni++) {
                rp[mi][0] += __expf(scale * acc[mi][ni][0]) + __expf(scale * acc[mi][ni][1]);
                rp[mi][1] += __expf(scale * acc[mi][ni][2]) + __expf(scale * acc[mi][ni][3]);
            }

        cp_wait<0>();
        __syncthreads();
    }

    #pragma unroll
    for (int mi = 0; mi < 2; mi++)
        #pragma unroll
        for (int hh = 0; hh < 2; hh++) {
            rp[mi][hh] += __shfl_xor_sync(0xffffffffu, rp[mi][hh], 1);
            rp[mi][hh] += __shfl_xor_sync(0xffffffffu, rp[mi][hh], 2);
        }
    if (tig == 0) {
        #pragma unroll
        for (int mi = 0; mi < 2; mi++)
            #pragma unroll
            for (int hh = 0; hh < 2; hh++)
                red[wn][wm0 + mi * 16 + gid + 8 * hh] = rp[mi][hh];
    }
    __syncthreads();
    if (tid < 128) {
        long row = (long)h * S_LEN + mb * 128 + tid;
        inv[row] = 1.0f / (red[0][tid] + red[1][tid]);
    }
}

// ---------------------------------------------------------------------------
// Fused attention, 64x64 tiles, occ 3, all-LDSM (V pre-transposed).
// 8 warps = 2 (M) x 4 (N), each 32x16.
// Smem: Qs[64][68] Ks[64][68] Vs[64][68] Ps[64][68] + invs[64]  (~70 KB)
// ---------------------------------------------------------------------------
__global__ void __launch_bounds__(256, 3)
fused_attn_kernel(const float* __restrict__ Qp, const float* __restrict__ Kp,
                  const float* __restrict__ Vt, const float* __restrict__ invp,
                  float* __restrict__ attn, float* __restrict__ vals, float scale)
{
    extern __shared__ __align__(16) float sm[];
    const int LD = D_HEAD + 4;
    float (*Qs)[D_HEAD + 4] = (float (*)[D_HEAD + 4])sm;
    float (*Ks)[D_HEAD + 4] = (float (*)[D_HEAD + 4])(sm + 64 * LD);
    float (*Vs)[D_HEAD + 4] = (float (*)[D_HEAD + 4])(sm + 128 * LD);
    float (*Ps)[D_HEAD + 4] = (float (*)[D_HEAD + 4])(sm + 192 * LD);
    float* invs = sm + 256 * LD;

    const int mb = blockIdx.x, h = blockIdx.y;
    const float* Aq = Qp + (long)mb * 64 * D_MODEL + h * D_HEAD;
    const float* Kg = Kp + h * D_HEAD;
    const float* Vg = Vt + (size_t)h * D_HEAD * S_LEN;   // rows d, stride S_LEN
    const long attn_row0 = (long)h * S_LEN + mb * 64;

    const int tid = threadIdx.x;
    const int warp = tid >> 5;
    const int lane = tid & 31;
    const int gid = lane >> 2;
    const int tig = lane & 3;
    const int wm0 = (warp >> 2) * 32;     // 2 warps along M
    const int wn0 = (warp & 3) * 16;      // 4 warps along N

    const int arow = lane & 15;
    const int acol = (lane >> 4) << 2;
    const int brow = (lane & 7) + ((lane >> 4) << 3);
    const int bcol = ((lane >> 3) & 1) << 2;

    // prologue: async K0; async V0; stage Q + inv
    #pragma unroll
    for (int i = 0; i < 4; i++) {
        int idx = tid + i * 256;
        int r = idx >> 4;
        int c4 = (idx & 15) * 4;
        cp_async16(smem_u32(&Ks[r][c4]), Kg + (long)r * D_MODEL + c4);
    }
    cp_commit();
    #pragma unroll
    for (int i = 0; i < 4; i++) {
        int idx = tid + i * 256;
        int r = idx >> 4;
        int c4 = (idx & 15) * 4;
        cp_async16(smem_u32(&Vs[r][c4]), Vg + (long)r * S_LEN + c4);
    }
    cp_commit();

    #pragma unroll
    for (int i = 0; i < 4; i++) {
        int idx = tid + i * 256;
        int r = idx >> 4;
        int c4 = (idx & 15) * 4;
        *(float4*)&Qs[r][c4] = *(const float4*)(Aq + (long)r * D_MODEL + c4);
    }
    if (tid < 64) invs[tid] = invp[attn_row0 + tid];

    uint32_t qa[2], pa[2];
    #pragma unroll
    for (int mi = 0; mi < 2; mi++) {
        qa[mi] = smem_u32(&Qs[wm0 + mi * 16 + arow][acol]);
        pa[mi] = smem_u32(&Ps[wm0 + mi * 16 + arow][acol]);
    }
    const uint32_t kba = smem_u32(&Ks[wn0 + brow][bcol]);
    const uint32_t vba = smem_u32(&Vs[wn0 + brow][bcol]);

    float oacc[2][2][4];
    #pragma unroll
    for (int mi = 0; mi < 2; mi++)
        #pragma unroll
        for (int ni = 0; ni < 2; ni++)
            #pragma unroll
            for (int j = 0; j < 4; j++) oacc[mi][ni][j] = 0.f;

    cp_wait<0>();
    __syncthreads();

    for (int nb = 0; nb < S_LEN / D_HEAD; nb++) {
        // ---- S = Q @ K^T (64x64) ----
        float acc[2][2][4];
        #pragma unroll
        for (int mi = 0; mi < 2; mi++)
            #pragma unroll
            for (int ni = 0; ni < 2; ni++)
                #pragma unroll
                for (int j = 0; j < 4; j++) acc[mi][ni][j] = 0.f;

        #pragma unroll
        for (int ksi = 0; ksi < 8; ksi++) {
            const uint32_t koff = ksi * 8 * 4;
            uint32_t a[2][4];
            #pragma unroll
            for (int mi = 0; mi < 2; mi++)
                ldsm_x4(a[mi][0], a[mi][1], a[mi][2], a[mi][3], qa[mi] + koff);
            uint32_t b[4];
            ldsm_x4(b[0], b[1], b[2], b[3], kba + koff);
            #pragma unroll
            for (int mi = 0; mi < 2; mi++)
                #pragma unroll
                for (int ni = 0; ni < 2; ni++) {
                    int hi = ni << 1;
                    mma_tf32u(acc[mi][ni][0], acc[mi][ni][1], acc[mi][ni][2], acc[mi][ni][3],
                              a[mi][0], a[mi][1], a[mi][2], a[mi][3],
                              b[hi], b[hi + 1]);
                }
        }

        // ---- p = exp(scale*s) * inv -> Ps ----
        #pragma unroll
        for (int mi = 0; mi < 2; mi++) {
            int r = wm0 + mi * 16 + gid;
            float iv0 = invs[r], iv1 = invs[r + 8];
            #pragma unroll
            for (int ni = 0; ni < 2; ni++) {
                int c = wn0 + ni * 8 + tig * 2;
                *(float2*)&Ps[r][c] =
                    make_float2(__expf(scale * acc[mi][ni][0]) * iv0,
                                __expf(scale * acc[mi][ni][1]) * iv0);
                *(float2*)&Ps[r + 8][c] =
                    make_float2(__expf(scale * acc[mi][ni][2]) * iv1,
                                __expf(scale * acc[mi][ni][3]) * iv1);
            }
        }

        cp_wait<0>();        // V(nb) complete
        __syncthreads();     // Ps ready; Ks fully consumed

        // ---- prefetch K(nb+1) (overlaps PV + attn store) ----
        if (nb + 1 < S_LEN / D_HEAD) {
            const float* gk = Kg + (long)(nb + 1) * 64 * D_MODEL;
            #pragma unroll
            for (int i = 0; i < 4; i++) {
                int idx = tid + i * 256;
                int r = idx >> 4;
                int c4 = (idx & 15) * 4;
                cp_async16(smem_u32(&Ks[r][c4]), gk + (long)r * D_MODEL + c4);
            }
        }
        cp_commit();

        // ---- O += Ps @ Vs (LDSM both sides) ----
        #pragma unroll
        for (int ksi = 0; ksi < 8; ksi++) {
            const uint32_t koff = ksi * 8 * 4;
            uint32_t a[2][4];
            #pragma unroll
            for (int mi = 0; mi < 2; mi++)
                ldsm_x4(a[mi][0], a[mi][1], a[mi][2], a[mi][3], pa[mi] + koff);
            uint32_t b[4];
            ldsm_x4(b[0], b[1], b[2], b[3], vba + koff);
            #pragma unroll
            for (int mi = 0; mi < 2; mi++)
                #pragma unroll
                for (int ni = 0; ni < 2; ni++) {
                    int hi = ni << 1;
                    mma_tf32u(oacc[mi][ni][0], oacc[mi][ni][1], oacc[mi][ni][2], oacc[mi][ni][3],
                              a[mi][0], a[mi][1], a[mi][2], a[mi][3],
                              b[hi], b[hi + 1]);
                }
        }

        // ---- attn tile write (64x64) from Ps ----
        #pragma unroll
        for (int i = 0; i < 4; i++) {
            int idx = tid + i * 256;
            int r = idx >> 4;
            int c4 = (idx & 15) * 4;
            *(float4*)&attn[(attn_row0 + r) * S_LEN + nb * 64 + c4] =
                *(const float4*)&Ps[r][c4];
        }

        __syncthreads();     // Vs and Ps fully consumed

        // ---- prefetch V(nb+1): Vt rows d, cols (nb+1)*64 ----
        if (nb + 1 < S_LEN / D_HEAD) {
            const float* gv = Vg + (long)(nb + 1) * 64;
            #pragma unroll
            for (int i = 0; i < 4; i++) {
                int idx = tid + i * 256;
                int r = idx >> 4;
                int c4 = (idx & 15) * 4;
                cp_async16(smem_u32(&Vs[r][c4]), gv + (long)r * S_LEN + c4);
            }
        }
        cp_commit();

        cp_wait<1>();        // K(nb+1) done
        __syncthreads();
    }

    // Epilogue: write O  (note PV computes O^T? no: A=P rows m, B=Vt rows d=n -> O[m][d])
    #pragma unroll
    for (int mi = 0; mi < 2; mi++) {
        int r0 = mb * 64 + wm0 + mi * 16 + gid;
        #pragma unroll
        for (int ni = 0; ni < 2; ni++) {
            int c = h * D_HEAD + wn0 + ni * 8 + tig * 2;
            *(float2*)&vals[(long)r0 * D_MODEL + c] =
                make_float2(oacc[mi][ni][0], oacc[mi][ni][1]);
            *(float2*)&vals[(long)(r0 + 8) * D_MODEL + c] =
                make_float2(oacc[mi][ni][2], oacc[mi][ni][3]);
        }
    }
}

extern "C" void kernel_launch(void* const* d_in, const int* in_sizes, int n_in,
                              void* d_out, int out_size)
{
    const float* q  = (const float*)d_in[0];
    const float* k  = (const float*)d_in[1];
    const float* v  = (const float*)d_in[2];
    const float* Wq = (const float*)d_in[3];
    const float* bq = (const float*)d_in[4];
    const float* Wk = (const float*)d_in[5];
    const float* bk = (const float*)d_in[6];
    const float* Wv = (const float*)d_in[7];
    const float* bv = (const float*)d_in[8];
    const float* Wo = (const float*)d_in[9];
    const float* bo = (const float*)d_in[10];

    float* out = (float*)d_out;

    float *Qp, *Kp, *Vp, *Vt, *Vals, *Wt, *Inv, *attn_fb;
    cudaGetSymbolAddress((void**)&Qp,   g_Qp);
    cudaGetSymbolAddress((void**)&Kp,   g_Kp);
    cudaGetSymbolAddress((void**)&Vp,   g_Vp);
    cudaGetSymbolAddress((void**)&Vt,   g_Vt);
    cudaGetSymbolAddress((void**)&Vals, g_vals);
    cudaGetSymbolAddress((void**)&Wt,   g_Wt);
    cudaGetSymbolAddress((void**)&Inv,  g_inv);
    cudaGetSymbolAddress((void**)&attn_fb, g_attn_fallback);

    const long OUT_ELEMS  = (long)S_LEN * D_MODEL;
    const long ATTN_ELEMS = (long)N_HEADS * S_LEN * S_LEN;
    float* attn = ((long)out_size >= OUT_ELEMS + ATTN_ELEMS)
                      ? (out + OUT_ELEMS)
                      : attn_fb;

    const int LD = D_HEAD + 4;
    const int ROWSUM_SMEM = 3 * 128 * LD * (int)sizeof(float);           // ~102 KB
    const int FUSED_SMEM  = (256 * LD + 64) * (int)sizeof(float);        // ~70 KB
    static bool attr_done = false;
    if (!attr_done) {
        cudaFuncSetAttribute(rowsum_kernel,
                             cudaFuncAttributeMaxDynamicSharedMemorySize, ROWSUM_SMEM);
        cudaFuncSetAttribute(fused_attn_kernel,
                             cudaFuncAttributeMaxDynamicSharedMemorySize, FUSED_SMEM);
        attr_done = true;
    }

    dim3 blk(256);
    const float scale = 1.0f / sqrtf((float)D_HEAD);

    // 0) Transpose + tf32-round all four weight matrices
    transpose_w<<<dim3(32, 32, 4), dim3(32, 8)>>>(Wq, Wk, Wv, Wo, Wt);

    // 1) QKV projections (NT, dual-LDSM), outputs pre-rounded to tf32
    dim3 gQKV(D_MODEL / 128, S_LEN / 128, 3);
    qkv_proj<<<gQKV, blk>>>(q, k, v, Wt, bq, bk, bv, Qp, Kp, Vp);

    // 1b) Per-head V transpose (already tf32)
    transpose_v<<<dim3(S_LEN / 32, D_HEAD / 32, N_HEADS), dim3(32, 8)>>>(Vp, Vt);

    // 2) Row sums -> inv (double-buffered cp.async)
    dim3 gRS(S_LEN / 128, N_HEADS);
    rowsum_kernel<<<gRS, blk, ROWSUM_SMEM>>>(Qp, Kp, Inv, scale);

    // 3) Fused: 64x64 tiles, occ 3, all-LDSM
    dim3 gF(S_LEN / 64, N_HEADS);
    fused_attn_kernel<<<gF, blk, FUSED_SMEM>>>(Qp, Kp, Vt, Inv, attn, Vals, scale);

    // 4) out = vals @ Wo + bo (fp32 output)
    dim3 gProj(D_MODEL / 128, S_LEN / 128, 1);
    o_proj<<<gProj, blk>>>(Vals, Wt, out, bo);
}